// round 14
// baseline (speedup 1.0000x reference)
#include <cuda_runtime.h>
#include <cuda_bf16.h>
#include <cstdint>

#define BATCH 4
#define SLEN  4096
#define DDIM  1024
#define WIN   256
#define SPAD  (SLEN + 2 * WIN)        // 4608 padded seq rows (zeros in pads)
#define NCOL  (128 + 2 * WIN)         // 640 band columns per 128-query tile
#define QT_PER_B (SLEN / 128)
#define NEGV  (-1e10f)
#define RSTR  12                      // u32 row stride in smem (8 data + 4 pad)

// ---- split bf16 scratch (device globals: zero-init; pads never written) ----
__device__ uint16_t c_Xh[(size_t)BATCH * SLEN * DDIM];
__device__ uint16_t c_Xl[(size_t)BATCH * SLEN * DDIM];
__device__ uint16_t c_Yh[(size_t)BATCH * SLEN * DDIM];
__device__ uint16_t c_Yl[(size_t)BATCH * SLEN * DDIM];
__device__ uint16_t c_Wqh[DDIM * DDIM], c_Wql[DDIM * DDIM];
__device__ uint16_t c_Wkh[DDIM * DDIM], c_Wkl[DDIM * DDIM];
__device__ uint16_t c_Wvh[DDIM * DDIM], c_Wvl[DDIM * DDIM];
__device__ uint16_t g_Qh[(size_t)BATCH * SLEN * DDIM];
__device__ uint16_t g_Ql[(size_t)BATCH * SLEN * DDIM];
__device__ uint16_t g_Kh[(size_t)BATCH * SPAD * DDIM];
__device__ uint16_t g_Kl[(size_t)BATCH * SPAD * DDIM];
__device__ uint16_t g_Vth[(size_t)BATCH * DDIM * SPAD];   // V^T: [b][d][seq_pad]
__device__ uint16_t g_Vtl[(size_t)BATCH * DDIM * SPAD];
__device__ float    g_P [(size_t)BATCH * SLEN * NCOL];     // masked scores (f32)
__device__ uint16_t g_Ph[(size_t)BATCH * SLEN * NCOL];     // softmax probs split
__device__ uint16_t g_Pl[(size_t)BATCH * SLEN * NCOL];

// ---------------------------------------------------------------------------
__device__ __forceinline__ void cvt_split2(float f0, float f1, uint32_t& hi, uint32_t& lo)
{
    asm("cvt.rn.bf16x2.f32 %0, %1, %2;" : "=r"(hi) : "f"(f1), "f"(f0));
    float h0 = __uint_as_float(hi << 16);
    float h1 = __uint_as_float(hi & 0xffff0000u);
    asm("cvt.rn.bf16x2.f32 %0, %1, %2;" : "=r"(lo) : "f"(f1 - h1), "f"(f0 - h0));
}
__device__ __forceinline__ void mma16816(float* d, const uint32_t* a, const uint32_t* b)
{
    asm volatile(
        "mma.sync.aligned.m16n8k16.row.col.f32.bf16.bf16.f32 "
        "{%0,%1,%2,%3}, {%4,%5,%6,%7}, {%8,%9}, {%0,%1,%2,%3};"
        : "+f"(d[0]), "+f"(d[1]), "+f"(d[2]), "+f"(d[3])
        : "r"(a[0]), "r"(a[1]), "r"(a[2]), "r"(a[3]), "r"(b[0]), "r"(b[1]));
}

// ---------------------------------------------------------------------------
// One-time fp32 -> (bf16 hi, bf16 lo) split
// ---------------------------------------------------------------------------
__global__ void __launch_bounds__(256) split_kernel(const float4* __restrict__ src,
                                                    uint2* __restrict__ dh,
                                                    uint2* __restrict__ dl, int n4)
{
    int i = blockIdx.x * blockDim.x + threadIdx.x;
    if (i < n4) {
        float4 v = src[i];
        uint32_t h0, l0, h1, l1;
        cvt_split2(v.x, v.y, h0, l0);
        cvt_split2(v.z, v.w, h1, l1);
        dh[i] = make_uint2(h0, h1);
        dl[i] = make_uint2(l0, l1);
    }
}

// ---------------------------------------------------------------------------
// Unified GEMM: D[128,128] = (Ah+Al)[128,K] * (Bh+Bl)[128,K]^T, 3-term split.
// R3 pipeline exactly; operands pre-split; natural registers (occ target 1).
// MODE 0: Q proj   1: K proj (padded)   2: V proj (transposed out)
// MODE 3: banded scores (mask)          4: attn*V (final output)
// ---------------------------------------------------------------------------
template<int MODE>
__global__ void __launch_bounds__(256, 1) gemm_kernel(const uint16_t* __restrict__ Ah_,
                                                      const uint16_t* __restrict__ Al_,
                                                      const uint16_t* __restrict__ Bh_,
                                                      const uint16_t* __restrict__ Bl_,
                                                      float* __restrict__ Cg)
{
    // [stage][Ah, Al, Bh, Bl][128 rows * RSTR u32]  = 49152 bytes (conflict-free)
    __shared__ uint32_t sm[2][4][128 * RSTR];

    const int tid = threadIdx.x;
    const int wid = tid >> 5;
    const int lid = tid & 31;
    const int g   = lid >> 2;          // 0..7
    const int tig = lid & 3;           // 0..3
    const int warpM = (wid & 3) * 32;
    const int warpN = (wid >> 2) * 64;

    // ---- geometry ----
    const uint16_t *AhP, *AlP, *BhP, *BlP;
    long sA, sB;
    int nc, b = 0, qbase = 0, nt = 0, m0 = 0, n0 = 0;
    if constexpr (MODE <= 2) {
        n0 = blockIdx.x * 128; m0 = blockIdx.y * 128;
        AhP = Ah_ + (size_t)m0 * DDIM; AlP = Al_ + (size_t)m0 * DDIM;
        BhP = Bh_ + (size_t)n0 * DDIM; BlP = Bl_ + (size_t)n0 * DDIM;
        sA = DDIM; sB = DDIM; nc = DDIM / 16;
    } else if constexpr (MODE == 3) {
        int t = blockIdx.y; b = t / QT_PER_B; qbase = (t % QT_PER_B) * 128;
        nt = blockIdx.x;
        size_t ao = (size_t)(b * SLEN + qbase) * DDIM;
        size_t bo = ((size_t)b * SPAD + qbase + nt * 128) * DDIM;
        AhP = g_Qh + ao; AlP = g_Ql + ao; BhP = g_Kh + bo; BlP = g_Kl + bo;
        sA = DDIM; sB = DDIM; nc = DDIM / 16;
    } else {
        int t = blockIdx.y; b = t / QT_PER_B; qbase = (t % QT_PER_B) * 128;
        n0 = blockIdx.x * 128;
        size_t ao = (size_t)(b * SLEN + qbase) * NCOL;
        size_t bo = ((size_t)b * DDIM + n0) * SPAD + qbase;
        AhP = g_Ph + ao; AlP = g_Pl + ao; BhP = g_Vth + bo; BlP = g_Vtl + bo;
        sA = NCOL; sB = SPAD; nc = NCOL / 16;
    }

    // ---- producer mapping: thread -> (row, k-half of 8 bf16 = 16B) ----
    const int pr = tid >> 1;           // 0..127
    const int ph = tid & 1;            // 0/1
    const uint16_t* pAh = AhP + (size_t)pr * sA + ph * 8;
    const uint16_t* pAl = AlP + (size_t)pr * sA + ph * 8;
    const uint16_t* pBh = BhP + (size_t)pr * sB + ph * 8;
    const uint16_t* pBl = BlP + (size_t)pr * sB + ph * 8;
    const int sidx = pr * RSTR + ph * 4;

    float acc[2][8][4];
#pragma unroll
    for (int mt = 0; mt < 2; mt++)
#pragma unroll
        for (int n = 0; n < 8; n++)
#pragma unroll
            for (int e = 0; e < 4; e++) acc[mt][n][e] = 0.f;

    auto store_st = [&](int st, uint4 vah, uint4 val, uint4 vbh, uint4 vbl) {
        *(uint4*)&sm[st][0][sidx] = vah;
        *(uint4*)&sm[st][1][sidx] = val;
        *(uint4*)&sm[st][2][sidx] = vbh;
        *(uint4*)&sm[st][3][sidx] = vbl;
    };

    auto compute = [&](int st) {
        const uint32_t* sAh = sm[st][0];
        const uint32_t* sAl = sm[st][1];
        const uint32_t* sBh = sm[st][2];
        const uint32_t* sBl = sm[st][3];
        uint32_t ah[2][4], al[2][4];
#pragma unroll
        for (int mt = 0; mt < 2; mt++) {
            const int r0 = (warpM + mt * 16 + g) * RSTR;
            const int r8 = r0 + 8 * RSTR;
            ah[mt][0] = sAh[r0 + tig];     ah[mt][1] = sAh[r8 + tig];
            ah[mt][2] = sAh[r0 + tig + 4]; ah[mt][3] = sAh[r8 + tig + 4];
            al[mt][0] = sAl[r0 + tig];     al[mt][1] = sAl[r8 + tig];
            al[mt][2] = sAl[r0 + tig + 4]; al[mt][3] = sAl[r8 + tig + 4];
        }
#pragma unroll
        for (int n = 0; n < 8; n++) {
            const int c0 = (warpN + n * 8 + g) * RSTR;
            uint32_t bh[2], bl[2];
            bh[0] = sBh[c0 + tig]; bh[1] = sBh[c0 + tig + 4];
            bl[0] = sBl[c0 + tig]; bl[1] = sBl[c0 + tig + 4];
#pragma unroll
            for (int mt = 0; mt < 2; mt++) {
                mma16816(acc[mt][n], ah[mt], bh);
                mma16816(acc[mt][n], ah[mt], bl);
                mma16816(acc[mt][n], al[mt], bh);
            }
        }
    };

    // ---- prologue: chunk 0 ----
    store_st(0, *(const uint4*)pAh, *(const uint4*)pAl,
                *(const uint4*)pBh, *(const uint4*)pBl);
    __syncthreads();

    // ---- main loop: prefetch -> compute -> store-next -> barrier ----
    for (int c = 0; c < nc; c++) {
        uint4 nah, nal, nbh, nbl;
        const bool more = (c + 1 < nc);
        if (more) {
            const size_t o = (size_t)(c + 1) * 16;
            nah = *(const uint4*)(pAh + o);
            nal = *(const uint4*)(pAl + o);
            nbh = *(const uint4*)(pBh + o);
            nbl = *(const uint4*)(pBl + o);
        }
        compute(c & 1);
        if (more) store_st((c + 1) & 1, nah, nal, nbh, nbl);
        __syncthreads();
    }

    // ---- epilogue ----
#pragma unroll
    for (int mt = 0; mt < 2; mt++) {
#pragma unroll
        for (int n = 0; n < 8; n++) {
            const float* a = acc[mt][n];
            const int rlo = warpM + mt * 16 + g;
            const int rhi = rlo + 8;
            const int cn  = warpN + n * 8 + 2 * tig;
            if constexpr (MODE == 0 || MODE == 1) {
                const int mA = m0 + rlo, mB = m0 + rhi;
                size_t o0, o1;
                if constexpr (MODE == 0) {
                    o0 = (size_t)mA * DDIM + n0 + cn;
                    o1 = (size_t)mB * DDIM + n0 + cn;
                } else {
                    o0 = ((size_t)(mA >> 12) * SPAD + (mA & (SLEN - 1)) + WIN) * DDIM + n0 + cn;
                    o1 = ((size_t)(mB >> 12) * SPAD + (mB & (SLEN - 1)) + WIN) * DDIM + n0 + cn;
                }
                uint16_t* Hd = (MODE == 0) ? g_Qh : g_Kh;
                uint16_t* Ld = (MODE == 0) ? g_Ql : g_Kl;
                uint32_t h, l;
                cvt_split2(a[0], a[1], h, l);
                *(uint32_t*)(Hd + o0) = h; *(uint32_t*)(Ld + o0) = l;
                cvt_split2(a[2], a[3], h, l);
                *(uint32_t*)(Hd + o1) = h; *(uint32_t*)(Ld + o1) = l;
            } else if constexpr (MODE == 2) {
                const int mA = m0 + rlo, mB = m0 + rhi;
                const size_t dA = (size_t)(mA >> 12) * DDIM, qA = (mA & (SLEN - 1)) + WIN;
                const size_t dB = (size_t)(mB >> 12) * DDIM, qB = (mB & (SLEN - 1)) + WIN;
#pragma unroll
                for (int e = 0; e < 2; e++) {
                    {
                        float v = a[e];
                        __nv_bfloat16 hb = __float2bfloat16(v);
                        size_t off = (dA + n0 + cn + e) * SPAD + qA;
                        g_Vth[off] = __bfloat16_as_ushort(hb);
                        g_Vtl[off] = __bfloat16_as_ushort(__float2bfloat16(v - __bfloat162float(hb)));
                    }
                    {
                        float v = a[e + 2];
                        __nv_bfloat16 hb = __float2bfloat16(v);
                        size_t off = (dB + n0 + cn + e) * SPAD + qB;
                        g_Vth[off] = __bfloat16_as_ushort(hb);
                        g_Vtl[off] = __bfloat16_as_ushort(__float2bfloat16(v - __bfloat162float(hb)));
                    }
                }
            } else if constexpr (MODE == 3) {
                const int jb = qbase - WIN + nt * 128 + cn;
                float* p0 = g_P + (size_t)(b * SLEN + qbase + rlo) * NCOL + nt * 128 + cn;
                float* p1 = g_P + (size_t)(b * SLEN + qbase + rhi) * NCOL + nt * 128 + cn;
#pragma unroll
                for (int e = 0; e < 2; e++) {
                    const int jj = jb + e;
                    {
                        const int q = qbase + rlo, d = q - jj;
                        p0[e] = (jj >= 0 && jj < SLEN && d <= WIN && d >= -WIN)
                                ? a[e] * 0.03125f : NEGV;
                    }
                    {
                        const int q = qbase + rhi, d = q - jj;
                        p1[e] = (jj >= 0 && jj < SLEN && d <= WIN && d >= -WIN)
                                ? a[e + 2] * 0.03125f : NEGV;
                    }
                }
            } else {
                float* p0 = Cg + ((size_t)b * SLEN + qbase + rlo) * DDIM + n0 + cn;
                float* p1 = Cg + ((size_t)b * SLEN + qbase + rhi) * DDIM + n0 + cn;
                p0[0] = a[0]; p0[1] = a[1]; p1[0] = a[2]; p1[1] = a[3];
            }
        }
    }
}

// ---------------------------------------------------------------------------
// Row softmax over 640 band columns; writes probabilities in split bf16.
// ---------------------------------------------------------------------------
__global__ void __launch_bounds__(128) softmax_kernel()
{
    const int r = blockIdx.x;
    const float* row = g_P + (size_t)r * NCOL;
    const int tid = threadIdx.x;

    float v[5];
    float mx = NEGV;
#pragma unroll
    for (int i = 0; i < 5; i++) { v[i] = row[tid + i * 128]; mx = fmaxf(mx, v[i]); }
    __shared__ float red[4];
#pragma unroll
    for (int o = 16; o > 0; o >>= 1) mx = fmaxf(mx, __shfl_xor_sync(0xffffffffu, mx, o));
    if ((tid & 31) == 0) red[tid >> 5] = mx;
    __syncthreads();
    mx = fmaxf(fmaxf(red[0], red[1]), fmaxf(red[2], red[3]));

    float s = 0.f;
#pragma unroll
    for (int i = 0; i < 5; i++) { v[i] = __expf(v[i] - mx); s += v[i]; }
#pragma unroll
    for (int o = 16; o > 0; o >>= 1) s += __shfl_xor_sync(0xffffffffu, s, o);
    __syncthreads();
    if ((tid & 31) == 0) red[tid >> 5] = s;
    __syncthreads();
    const float inv = 1.0f / (red[0] + red[1] + red[2] + red[3]);
#pragma unroll
    for (int i = 0; i < 5; i++) {
        const float p = v[i] * inv;
        __nv_bfloat16 hb = __float2bfloat16(p);
        const size_t o = (size_t)r * NCOL + tid + i * 128;
        g_Ph[o] = __bfloat16_as_ushort(hb);
        g_Pl[o] = __bfloat16_as_ushort(__float2bfloat16(p - __bfloat162float(hb)));
    }
}

// ---------------------------------------------------------------------------
extern "C" void kernel_launch(void* const* d_in, const int* in_sizes, int n_in,
                              void* d_out, int out_size)
{
    (void)in_sizes; (void)n_in; (void)out_size;
    const float* X  = (const float*)d_in[0];
    const float* Y  = (const float*)d_in[1];
    const float* Wq = (const float*)d_in[2];
    const float* Wk = (const float*)d_in[3];
    const float* Wv = (const float*)d_in[4];
    float* out = (float*)d_out;

    static uint16_t *xh = nullptr, *xl, *yh, *yl, *wqh, *wql, *wkh, *wkl, *wvh, *wvl;
    if (!xh) {
        cudaGetSymbolAddress((void**)&xh,  c_Xh);  cudaGetSymbolAddress((void**)&xl,  c_Xl);
        cudaGetSymbolAddress((void**)&yh,  c_Yh);  cudaGetSymbolAddress((void**)&yl,  c_Yl);
        cudaGetSymbolAddress((void**)&wqh, c_Wqh); cudaGetSymbolAddress((void**)&wql, c_Wql);
        cudaGetSymbolAddress((void**)&wkh, c_Wkh); cudaGetSymbolAddress((void**)&wkl, c_Wkl);
        cudaGetSymbolAddress((void**)&wvh, c_Wvh); cudaGetSymbolAddress((void**)&wvl, c_Wvl);
    }

    const int nXY4 = BATCH * SLEN * DDIM / 4;
    const int nW4  = DDIM * DDIM / 4;
    split_kernel<<<(nXY4 + 255) / 256, 256>>>((const float4*)X, (uint2*)xh, (uint2*)xl, nXY4);
    split_kernel<<<(nXY4 + 255) / 256, 256>>>((const float4*)Y, (uint2*)yh, (uint2*)yl, nXY4);
    split_kernel<<<(nW4 + 255) / 256, 256>>>((const float4*)Wq, (uint2*)wqh, (uint2*)wql, nW4);
    split_kernel<<<(nW4 + 255) / 256, 256>>>((const float4*)Wk, (uint2*)wkh, (uint2*)wkl, nW4);
    split_kernel<<<(nW4 + 255) / 256, 256>>>((const float4*)Wv, (uint2*)wvh, (uint2*)wvl, nW4);

    const dim3 gProj(DDIM / 128, (BATCH * SLEN) / 128);   // (8, 128)
    gemm_kernel<0><<<gProj, 256>>>(yh, yl, wqh, wql, nullptr);   // Q
    gemm_kernel<1><<<gProj, 256>>>(xh, xl, wkh, wkl, nullptr);   // K (padded)
    gemm_kernel<2><<<gProj, 256>>>(xh, xl, wvh, wvl, nullptr);   // V (transposed)
    gemm_kernel<3><<<dim3(5, BATCH * QT_PER_B), 256>>>(nullptr, nullptr, nullptr, nullptr, nullptr);
    softmax_kernel<<<BATCH * SLEN, 128>>>();
    gemm_kernel<4><<<dim3(DDIM / 128, BATCH * QT_PER_B), 256>>>(nullptr, nullptr, nullptr, nullptr, out);
}

// round 15
// speedup vs baseline: 1.2051x; 1.2051x over previous
#include <cuda_runtime.h>
#include <cstdint>

#define BATCH 4
#define SLEN  4096
#define DDIM  1024
#define WIN   256
#define SPAD  (SLEN + 2 * WIN)        // 4608 padded seq rows (zeros in pads)
#define NCOL  (128 + 2 * WIN)         // 640 score columns per query tile
#define QT_PER_B (SLEN / 128)
#define NEGV  (-1e10f)
#define RSTR  12                      // u32 row stride in smem (16 data + pad)

// Scratch (device globals: allocation-free, zero-initialized once at load;
// pad rows of K/V scratch are never written so they stay zero).
__device__ float g_Q [(size_t)BATCH * SLEN * DDIM];
__device__ float g_K [(size_t)BATCH * SPAD * DDIM];
__device__ float g_Vt[(size_t)BATCH * DDIM * SPAD];   // V transposed: [b][d][seq_pad]
__device__ float g_P [(size_t)BATCH * SLEN * NCOL];

// ---------------------------------------------------------------------------
// bf16x2 split helpers
// ---------------------------------------------------------------------------
__device__ __forceinline__ void cvt_split2(float f0, float f1, uint32_t& hi, uint32_t& lo)
{
    // packed reg: low 16 bits = f0 (even k), high 16 = f1 (odd k)
    asm("cvt.rn.bf16x2.f32 %0, %1, %2;" : "=r"(hi) : "f"(f1), "f"(f0));
    float h0 = __uint_as_float(hi << 16);
    float h1 = __uint_as_float(hi & 0xffff0000u);
    float l0 = f0 - h0;
    float l1 = f1 - h1;
    asm("cvt.rn.bf16x2.f32 %0, %1, %2;" : "=r"(lo) : "f"(l1), "f"(l0));
}

__device__ __forceinline__ void mma16816(float* d, const uint32_t* a, const uint32_t* b)
{
    asm volatile(
        "mma.sync.aligned.m16n8k16.row.col.f32.bf16.bf16.f32 "
        "{%0,%1,%2,%3}, {%4,%5,%6,%7}, {%8,%9}, {%0,%1,%2,%3};"
        : "+f"(d[0]), "+f"(d[1]), "+f"(d[2]), "+f"(d[3])
        : "r"(a[0]), "r"(a[1]), "r"(a[2]), "r"(a[3]), "r"(b[0]), "r"(b[1]));
}

// ---------------------------------------------------------------------------
// Unified GEMM: D[128,128] = A[128,K] * B[128,K]^T (both operands K-major)
// MODE 0: Q proj   1: K proj (padded rows)   2: V proj (transposed out)
// MODE 3: banded scores (mask epilogue)      4: attn*V (final output)
// ---------------------------------------------------------------------------
template<int MODE>
__global__ void __launch_bounds__(256, 1) gemm_kernel(const float* __restrict__ Ag,
                                                      const float* __restrict__ Bg,
                                                      float* __restrict__ Cg)
{
    // [stage][Ah, Al, Bh, Bl][128 rows * RSTR u32]  = 49152 bytes
    __shared__ uint32_t sm[2][4][128 * RSTR];

    const int tid = threadIdx.x;
    const int wid = tid >> 5;
    const int lid = tid & 31;
    const int g   = lid >> 2;          // group id 0..7
    const int tig = lid & 3;           // thread in group
    const int warpM = (wid & 3) * 32;  // 4 warps along M
    const int warpN = (wid >> 2) * 64; // 2 warps along N

    // ---- per-mode geometry ----
    const float* Abase; const float* Bbase;
    long strideA, strideB;
    int nc, b = 0, qbase = 0, nt = 0, m0 = 0, n0 = 0;
    if constexpr (MODE <= 2) {
        n0 = blockIdx.x * 128; m0 = blockIdx.y * 128;
        Abase = Ag + (size_t)m0 * DDIM; strideA = DDIM;
        Bbase = Bg + (size_t)n0 * DDIM; strideB = DDIM;
        nc = DDIM / 16;
    } else if constexpr (MODE == 3) {
        int t = blockIdx.y; b = t / QT_PER_B; qbase = (t % QT_PER_B) * 128;
        nt = blockIdx.x;
        Abase = g_Q + (size_t)(b * SLEN + qbase) * DDIM;             strideA = DDIM;
        Bbase = g_K + ((size_t)b * SPAD + qbase + nt * 128) * DDIM;  strideB = DDIM;
        nc = DDIM / 16;
    } else {
        int t = blockIdx.y; b = t / QT_PER_B; qbase = (t % QT_PER_B) * 128;
        n0 = blockIdx.x * 128;
        Abase = g_P  + (size_t)(b * SLEN + qbase) * NCOL;            strideA = NCOL;
        Bbase = g_Vt + ((size_t)b * DDIM + n0) * SPAD + qbase;       strideB = SPAD;
        nc = NCOL / 16;   // 40
    }

    // ---- producer lanes: thread -> (row, k-half) ----
    const int pr = tid >> 1;           // 0..127
    const int ph = tid & 1;            // 0/1 -> k offset 8*ph
    const float* Ar = Abase + (size_t)pr * strideA + ph * 8;
    const float* Br = Bbase + (size_t)pr * strideB + ph * 8;
    const int sidx = pr * RSTR + ph * 4;

    float acc[2][8][4];
#pragma unroll
    for (int mt = 0; mt < 2; mt++)
#pragma unroll
        for (int ntile = 0; ntile < 8; ntile++)
#pragma unroll
            for (int e = 0; e < 4; e++) acc[mt][ntile][e] = 0.f;

    // ---- helpers as lambdas ----
    auto cvt_store = [&](int st, float4 a0, float4 a1, float4 b0, float4 b1) {
        uint32_t h[4], l[4];
        cvt_split2(a0.x, a0.y, h[0], l[0]); cvt_split2(a0.z, a0.w, h[1], l[1]);
        cvt_split2(a1.x, a1.y, h[2], l[2]); cvt_split2(a1.z, a1.w, h[3], l[3]);
        *(uint4*)&sm[st][0][sidx] = make_uint4(h[0], h[1], h[2], h[3]);
        *(uint4*)&sm[st][1][sidx] = make_uint4(l[0], l[1], l[2], l[3]);
        cvt_split2(b0.x, b0.y, h[0], l[0]); cvt_split2(b0.z, b0.w, h[1], l[1]);
        cvt_split2(b1.x, b1.y, h[2], l[2]); cvt_split2(b1.z, b1.w, h[3], l[3]);
        *(uint4*)&sm[st][2][sidx] = make_uint4(h[0], h[1], h[2], h[3]);
        *(uint4*)&sm[st][3][sidx] = make_uint4(l[0], l[1], l[2], l[3]);
    };

    auto compute = [&](int st) {
        const uint32_t* sAh = sm[st][0];
        const uint32_t* sAl = sm[st][1];
        const uint32_t* sBh = sm[st][2];
        const uint32_t* sBl = sm[st][3];
        uint32_t ah[2][4], al[2][4];
#pragma unroll
        for (int mt = 0; mt < 2; mt++) {
            const int r0 = (warpM + mt * 16 + g) * RSTR;
            const int r8 = r0 + 8 * RSTR;
            ah[mt][0] = sAh[r0 + tig];     ah[mt][1] = sAh[r8 + tig];
            ah[mt][2] = sAh[r0 + tig + 4]; ah[mt][3] = sAh[r8 + tig + 4];
            al[mt][0] = sAl[r0 + tig];     al[mt][1] = sAl[r8 + tig];
            al[mt][2] = sAl[r0 + tig + 4]; al[mt][3] = sAl[r8 + tig + 4];
        }
#pragma unroll
        for (int ntile = 0; ntile < 8; ntile++) {
            const int c0 = (warpN + ntile * 8 + g) * RSTR;
            uint32_t bh[2], bl[2];
            bh[0] = sBh[c0 + tig]; bh[1] = sBh[c0 + tig + 4];
            bl[0] = sBl[c0 + tig]; bl[1] = sBl[c0 + tig + 4];
#pragma unroll
            for (int mt = 0; mt < 2; mt++) {
                mma16816(acc[mt][ntile], ah[mt], bh);
                mma16816(acc[mt][ntile], ah[mt], bl);
                mma16816(acc[mt][ntile], al[mt], bh);
            }
        }
    };

    // ---- prologue: chunk 0 ----
    {
        float4 a0 = *(const float4*)(Ar);
        float4 a1 = *(const float4*)(Ar + 4);
        float4 b0 = *(const float4*)(Br);
        float4 b1 = *(const float4*)(Br + 4);
        cvt_store(0, a0, a1, b0, b1);
    }
    __syncthreads();

    // ---- main loop ----
    for (int c = 0; c < nc; c++) {
        float4 na0, na1, nb0, nb1;
        const bool more = (c + 1 < nc);
        if (more) {
            const float* ap = Ar + (size_t)(c + 1) * 16;
            const float* bp = Br + (size_t)(c + 1) * 16;
            na0 = *(const float4*)(ap);
            na1 = *(const float4*)(ap + 4);
            nb0 = *(const float4*)(bp);
            nb1 = *(const float4*)(bp + 4);
        }
        compute(c & 1);
        if (more) cvt_store((c + 1) & 1, na0, na1, nb0, nb1);
        __syncthreads();
    }

    // ---- epilogue ----
#pragma unroll
    for (int mt = 0; mt < 2; mt++) {
#pragma unroll
        for (int ntile = 0; ntile < 8; ntile++) {
            const float* a = acc[mt][ntile];
            const int rlo = warpM + mt * 16 + g;
            const int rhi = rlo + 8;
            const int cn  = warpN + ntile * 8 + 2 * tig;
            if constexpr (MODE == 0) {
                float* p0 = g_Q + (size_t)(m0 + rlo) * DDIM + n0 + cn;
                float* p1 = g_Q + (size_t)(m0 + rhi) * DDIM + n0 + cn;
                p0[0] = a[0]; p0[1] = a[1]; p1[0] = a[2]; p1[1] = a[3];
            } else if constexpr (MODE == 1) {
                const int mA = m0 + rlo, mB = m0 + rhi;
                float* p0 = g_K + ((size_t)(mA >> 12) * SPAD + (mA & (SLEN - 1)) + WIN) * DDIM + n0 + cn;
                float* p1 = g_K + ((size_t)(mB >> 12) * SPAD + (mB & (SLEN - 1)) + WIN) * DDIM + n0 + cn;
                p0[0] = a[0]; p0[1] = a[1]; p1[0] = a[2]; p1[1] = a[3];
            } else if constexpr (MODE == 2) {
                const int mA = m0 + rlo, mB = m0 + rhi;
                const size_t sA = (size_t)(mA >> 12) * DDIM, qA = (mA & (SLEN - 1)) + WIN;
                const size_t sB = (size_t)(mB >> 12) * DDIM, qB = (mB & (SLEN - 1)) + WIN;
                g_Vt[(sA + n0 + cn)     * SPAD + qA] = a[0];
                g_Vt[(sA + n0 + cn + 1) * SPAD + qA] = a[1];
                g_Vt[(sB + n0 + cn)     * SPAD + qB] = a[2];
                g_Vt[(sB + n0 + cn + 1) * SPAD + qB] = a[3];
            } else if constexpr (MODE == 3) {
                const int jbase = qbase - WIN + nt * 128 + cn;
                float* p0 = g_P + (size_t)(b * SLEN + qbase + rlo) * NCOL + nt * 128 + cn;
                float* p1 = g_P + (size_t)(b * SLEN + qbase + rhi) * NCOL + nt * 128 + cn;
#pragma unroll
                for (int e = 0; e < 2; e++) {
                    const int jj = jbase + e;
                    {
                        const int q = qbase + rlo, d = q - jj;
                        p0[e] = (jj >= 0 && jj < SLEN && d <= WIN && d >= -WIN)
                                ? a[e] * 0.03125f : NEGV;
                    }
                    {
                        const int q = qbase + rhi, d = q - jj;
                        p1[e] = (jj >= 0 && jj < SLEN && d <= WIN && d >= -WIN)
                                ? a[e + 2] * 0.03125f : NEGV;
                    }
                }
            } else {
                float* p0 = Cg + ((size_t)b * SLEN + qbase + rlo) * DDIM + n0 + cn;
                float* p1 = Cg + ((size_t)b * SLEN + qbase + rhi) * DDIM + n0 + cn;
                p0[0] = a[0]; p0[1] = a[1]; p1[0] = a[2]; p1[1] = a[3];
            }
        }
    }
}

// ---------------------------------------------------------------------------
// Row softmax over the 640 band columns (masked entries = -1e10 -> exp = 0).
// ---------------------------------------------------------------------------
__global__ void __launch_bounds__(128) softmax_kernel()
{
    const int r   = blockIdx.x;                 // 0..BATCH*SLEN-1
    float* row    = g_P + (size_t)r * NCOL;
    const int tid = threadIdx.x;

    float v[5];
    float mx = NEGV;
#pragma unroll
    for (int i = 0; i < 5; i++) {
        v[i] = row[tid + i * 128];
        mx = fmaxf(mx, v[i]);
    }
    __shared__ float red[4];
#pragma unroll
    for (int o = 16; o > 0; o >>= 1) mx = fmaxf(mx, __shfl_xor_sync(0xffffffffu, mx, o));
    if ((tid & 31) == 0) red[tid >> 5] = mx;
    __syncthreads();
    mx = fmaxf(fmaxf(red[0], red[1]), fmaxf(red[2], red[3]));

    float s = 0.f;
#pragma unroll
    for (int i = 0; i < 5; i++) {
        v[i] = __expf(v[i] - mx);
        s += v[i];
    }
#pragma unroll
    for (int o = 16; o > 0; o >>= 1) s += __shfl_xor_sync(0xffffffffu, s, o);
    __syncthreads();
    if ((tid & 31) == 0) red[tid >> 5] = s;
    __syncthreads();
    const float inv = 1.0f / (red[0] + red[1] + red[2] + red[3]);
#pragma unroll
    for (int i = 0; i < 5; i++) row[tid + i * 128] = v[i] * inv;
}

// ---------------------------------------------------------------------------
extern "C" void kernel_launch(void* const* d_in, const int* in_sizes, int n_in,
                              void* d_out, int out_size)
{
    (void)in_sizes; (void)n_in; (void)out_size;
    const float* X  = (const float*)d_in[0];
    const float* Y  = (const float*)d_in[1];
    const float* Wq = (const float*)d_in[2];
    const float* Wk = (const float*)d_in[3];
    const float* Wv = (const float*)d_in[4];
    float* out = (float*)d_out;

    // One-time (first, uncaptured call): side stream + fork/join events.
    static cudaStream_t sV = nullptr;
    static cudaEvent_t evRoot = nullptr, evV = nullptr;
    if (!sV) {
        cudaStreamCreateWithFlags(&sV, cudaStreamNonBlocking);
        cudaEventCreateWithFlags(&evRoot, cudaEventDisableTiming);
        cudaEventCreateWithFlags(&evV, cudaEventDisableTiming);
    }

    const dim3 gProj(DDIM / 128, (BATCH * SLEN) / 128);   // (8, 128)

    // Fork: V projection runs on sV, independent until the AV GEMM.
    cudaEventRecord(evRoot, 0);
    cudaStreamWaitEvent(sV, evRoot, 0);
    gemm_kernel<2><<<gProj, 256, 0, sV>>>(X, Wv, nullptr);   // V (transposed)
    cudaEventRecord(evV, sV);

    // Main chain on the default (capture) stream.
    gemm_kernel<0><<<gProj, 256>>>(Y, Wq, nullptr);          // Q = Y Wq^T
    gemm_kernel<1><<<gProj, 256>>>(X, Wk, nullptr);          // K (padded rows)
    gemm_kernel<3><<<dim3(5, BATCH * QT_PER_B), 256>>>(nullptr, nullptr, nullptr);
    softmax_kernel<<<BATCH * SLEN, 128>>>();

    // Join: AV needs V.
    cudaStreamWaitEvent(0, evV, 0);
    gemm_kernel<4><<<dim3(DDIM / 128, BATCH * QT_PER_B), 256>>>(nullptr, nullptr, out);
}